// round 7
// baseline (speedup 1.0000x reference)
#include <cuda_runtime.h>
#include <cstdint>

// Problem constants (GCN_59846074302981): N=50000, E=800000, F=H=128, C=8
#define MAX_N 50000
#define MAX_E 800000

// ---------------------------------------------------------------------------
// Scratch (allocation-free device globals)
// ---------------------------------------------------------------------------
__device__ __align__(16) float g_bufA[MAX_N * 128];  // GEMM out / agg in
__device__ __align__(16) float g_bufB[MAX_N * 128];  // agg out / next GEMM in
__device__ __align__(16) float g_dinv[MAX_N];
__device__ int   g_count[MAX_N];                     // histogram, then fill cursor
__device__ int   g_off[MAX_N + 1];                   // CSR offsets (by dest col)
__device__ int   g_srcIdx[MAX_E];                    // source node per CSR slot
__device__ int   g_stride;                           // 1 = int32 edge data, 2 = int64

__device__ __forceinline__ int edge_at(const int* __restrict__ buf, long j, int stride) {
    return buf[j * stride];
}

// ---------------------------------------------------------------------------
// init: zero counts; warp 0 of block 0 probes edge dtype in parallel.
// int64 data with indices < 2^31 has every odd int32 word == 0.
// 8 independent loads per lane + ballot => ~1 memory round trip.
// ---------------------------------------------------------------------------
__global__ void k_init(const int* __restrict__ ebuf, int n) {
    int i = blockIdx.x * blockDim.x + threadIdx.x;
    if (i < n) g_count[i] = 0;
    if (blockIdx.x == 0 && threadIdx.x < 32) {
        int lane = threadIdx.x;
        int nz = 0;
        #pragma unroll
        for (int t = 0; t < 8; t++)
            nz |= ebuf[2 * (lane + 32 * t) + 1];
        unsigned m = __ballot_sync(0xffffffffu, nz != 0);
        if (lane == 0) g_stride = (m == 0) ? 2 : 1;
    }
}

__global__ void k_hist(const int* __restrict__ ebuf, int e, int n) {
    int i = blockIdx.x * blockDim.x + threadIdx.x;
    if (i >= e) return;
    int st = g_stride;
    int c = edge_at(ebuf, (long)e + i, st);
    if ((unsigned)c < (unsigned)n) atomicAdd(&g_count[c], 1);
}

// Single-block scan. Also computes dinv and re-zeroes counts (fill cursors).
__global__ __launch_bounds__(1024) void k_scan(int n) {
    const int T = 1024;
    int tid  = threadIdx.x;
    int L    = (n + T - 1) / T;
    int beg  = tid * L;
    int end  = beg + L; if (end > n) end = n;

    int s = 0;
    for (int i = beg; i < end; i++) s += g_count[i];

    __shared__ int wsum[32];
    int lane = tid & 31, wid = tid >> 5;
    int v = s;
    #pragma unroll
    for (int o = 1; o < 32; o <<= 1) {
        int t = __shfl_up_sync(0xffffffffu, v, o);
        if (lane >= o) v += t;
    }
    if (lane == 31) wsum[wid] = v;
    __syncthreads();
    if (wid == 0) {
        int w = wsum[lane];
        #pragma unroll
        for (int o = 1; o < 32; o <<= 1) {
            int t = __shfl_up_sync(0xffffffffu, w, o);
            if (lane >= o) w += t;
        }
        wsum[lane] = w;
    }
    __syncthreads();

    int run = v - s + (wid ? wsum[wid - 1] : 0);
    for (int i = beg; i < end; i++) {
        int c = g_count[i];
        g_off[i]   = run;
        g_dinv[i]  = rsqrtf((float)c + 1.0f);   // +1 self-loop
        g_count[i] = 0;                          // cursor for fill
        run += c;
    }
    if (tid == T - 1) g_off[n] = run;
}

// Fill: only source index per CSR slot; edge weight recomputed in aggregate.
__global__ void k_fill(const int* __restrict__ ebuf, int e, int n) {
    int i = blockIdx.x * blockDim.x + threadIdx.x;
    if (i >= e) return;
    int st = g_stride;
    int r = edge_at(ebuf, i, st);
    int c = edge_at(ebuf, (long)e + i, st);
    if ((unsigned)r >= (unsigned)n || (unsigned)c >= (unsigned)n) return;
    int slot = g_off[c] + atomicAdd(&g_count[c], 1);
    g_srcIdx[slot] = r;
}

// ---------------------------------------------------------------------------
// GEMM: g_bufA[n,128] = SRC[n,128] @ W[128,128]
// (round-3 known-good config) 64x128 tile, BK=32, 256 thr, 4x8 per thread.
// ---------------------------------------------------------------------------
__global__ __launch_bounds__(256) void k_gemm128(const float* __restrict__ Xext,
                                                 const float* __restrict__ W,
                                                 int use_ext, int nrows) {
    const float* __restrict__ X = use_ext ? Xext : g_bufB;
    __shared__ __align__(16) float xs[32][64 + 4];   // [k][m], padded
    __shared__ __align__(16) float ws[32][128];      // [k][n]

    const int row0 = blockIdx.x * 64;
    const int tid  = threadIdx.x;
    const int tm   = (tid >> 4) << 2;   // 0..60 step 4
    const int tn   = (tid & 15) << 3;   // 0..120 step 8

    float acc[4][8];
    #pragma unroll
    for (int i = 0; i < 4; i++)
        #pragma unroll
        for (int j = 0; j < 8; j++) acc[i][j] = 0.0f;

    for (int kk = 0; kk < 128; kk += 32) {
        #pragma unroll
        for (int i = 0; i < 2; i++) {
            int s  = tid + i * 256;      // 0..511
            int r  = s >> 3;             // 0..63
            int c4 = s & 7;              // float4 slot within 32-wide K chunk
            float4 v = make_float4(0.f, 0.f, 0.f, 0.f);
            if (row0 + r < nrows)
                v = reinterpret_cast<const float4*>(X)[(long)(row0 + r) * 32 + (kk >> 2) + c4];
            int kb = c4 << 2;
            xs[kb + 0][r] = v.x; xs[kb + 1][r] = v.y;
            xs[kb + 2][r] = v.z; xs[kb + 3][r] = v.w;
        }
        #pragma unroll
        for (int i = 0; i < 4; i++) {
            int s  = tid + i * 256;      // 0..1023
            int k  = s >> 5;             // 0..31
            int c4 = s & 31;
            reinterpret_cast<float4*>(ws[k])[c4] =
                reinterpret_cast<const float4*>(W)[(kk + k) * 32 + c4];
        }
        __syncthreads();

        #pragma unroll
        for (int k = 0; k < 32; k++) {
            float a[4] = {xs[k][tm + 0], xs[k][tm + 1], xs[k][tm + 2], xs[k][tm + 3]};
            float4 b0 = reinterpret_cast<const float4*>(ws[k])[(tn >> 2) + 0];
            float4 b1 = reinterpret_cast<const float4*>(ws[k])[(tn >> 2) + 1];
            float b[8] = {b0.x, b0.y, b0.z, b0.w, b1.x, b1.y, b1.z, b1.w};
            #pragma unroll
            for (int i = 0; i < 4; i++)
                #pragma unroll
                for (int j = 0; j < 8; j++)
                    acc[i][j] += a[i] * b[j];
        }
        __syncthreads();
    }

    #pragma unroll
    for (int i = 0; i < 4; i++) {
        int r = row0 + tm + i;
        if (r < nrows) {
            reinterpret_cast<float4*>(g_bufA)[(long)r * 32 + (tn >> 2) + 0] =
                make_float4(acc[i][0], acc[i][1], acc[i][2], acc[i][3]);
            reinterpret_cast<float4*>(g_bufA)[(long)r * 32 + (tn >> 2) + 1] =
                make_float4(acc[i][4], acc[i][5], acc[i][6], acc[i][7]);
        }
    }
}

// ---------------------------------------------------------------------------
// Aggregation (atomic-free): one warp per node, lane owns one float4 of H=128.
// result = bias + dinv^2 * h[node] + sum_{e->node} dinv[src]*dinv[node] * h[src]
// If Wfc != nullptr: fused classifier, writes out[node,8]; else writes g_bufB.
// ---------------------------------------------------------------------------
__global__ __launch_bounds__(256) void k_aggregate(const float* __restrict__ bias,
                                                   const float* __restrict__ Wfc,
                                                   const float* __restrict__ bfc,
                                                   float* __restrict__ out, int n) {
    __shared__ __align__(16) float wfcT[8][128];   // [c][k]
    __shared__ float bs[8];

    const int tid  = threadIdx.x;
    const int lane = tid & 31;
    const int fc   = (Wfc != nullptr);

    if (fc) {
        #pragma unroll
        for (int i = 0; i < 4; i++) {
            int idx = tid + i * 256;           // 0..1023 over Wfc[128][8]
            wfcT[idx & 7][idx >> 3] = Wfc[idx];
        }
        if (tid < 8) bs[tid] = bfc[tid];
        __syncthreads();
    }

    int warp = blockIdx.x * (blockDim.x >> 5) + (tid >> 5);
    if (warp >= n) return;

    const float4* __restrict__ h4 = reinterpret_cast<const float4*>(g_bufA);

    float d = g_dinv[warp];
    float4 b  = reinterpret_cast<const float4*>(bias)[lane];
    float4 hv = h4[(long)warp * 32 + lane];
    float s = d * d;
    float ax = b.x + s * hv.x, ay = b.y + s * hv.y;
    float az = b.z + s * hv.z, aw = b.w + s * hv.w;

    int j   = g_off[warp];
    int end = g_off[warp + 1];

    for (; j + 3 < end; j += 4) {
        int   r0 = g_srcIdx[j],     r1 = g_srcIdx[j + 1];
        int   r2 = g_srcIdx[j + 2], r3 = g_srcIdx[j + 3];
        float w0 = g_dinv[r0] * d,  w1 = g_dinv[r1] * d;
        float w2 = g_dinv[r2] * d,  w3 = g_dinv[r3] * d;
        float4 v0 = h4[(long)r0 * 32 + lane];
        float4 v1 = h4[(long)r1 * 32 + lane];
        float4 v2 = h4[(long)r2 * 32 + lane];
        float4 v3 = h4[(long)r3 * 32 + lane];
        ax += w0 * v0.x; ay += w0 * v0.y; az += w0 * v0.z; aw += w0 * v0.w;
        ax += w1 * v1.x; ay += w1 * v1.y; az += w1 * v1.z; aw += w1 * v1.w;
        ax += w2 * v2.x; ay += w2 * v2.y; az += w2 * v2.z; aw += w2 * v2.w;
        ax += w3 * v3.x; ay += w3 * v3.y; az += w3 * v3.z; aw += w3 * v3.w;
    }
    for (; j < end; j++) {
        int   r0 = g_srcIdx[j];
        float w0 = g_dinv[r0] * d;
        float4 v0 = h4[(long)r0 * 32 + lane];
        ax += w0 * v0.x; ay += w0 * v0.y; az += w0 * v0.z; aw += w0 * v0.w;
    }

    if (!fc) {
        reinterpret_cast<float4*>(g_bufB)[(long)warp * 32 + lane] =
            make_float4(ax, ay, az, aw);
    } else {
        float y[8];
        #pragma unroll
        for (int c = 0; c < 8; c++) {
            float4 w = *reinterpret_cast<const float4*>(&wfcT[c][lane << 2]);
            y[c] = ax * w.x + ay * w.y + az * w.z + aw * w.w;
        }
        #pragma unroll
        for (int o = 16; o > 0; o >>= 1)
            #pragma unroll
            for (int c = 0; c < 8; c++)
                y[c] += __shfl_xor_sync(0xffffffffu, y[c], o);
        if (lane == 0) {
            reinterpret_cast<float4*>(out)[(long)warp * 2 + 0] =
                make_float4(y[0] + bs[0], y[1] + bs[1], y[2] + bs[2], y[3] + bs[3]);
            reinterpret_cast<float4*>(out)[(long)warp * 2 + 1] =
                make_float4(y[4] + bs[4], y[5] + bs[5], y[6] + bs[6], y[7] + bs[7]);
        }
    }
}

// ---------------------------------------------------------------------------
// Launcher
// ---------------------------------------------------------------------------
extern "C" void kernel_launch(void* const* d_in, const int* in_sizes, int n_in,
                              void* d_out, int out_size) {
    const float* x   = (const float*)d_in[0];
    const int*   ei  = (const int*)d_in[1];   // int32 view; stride handles int64
    const float* W1  = (const float*)d_in[2];
    const float* b1  = (const float*)d_in[3];
    const float* W2  = (const float*)d_in[4];
    const float* b2  = (const float*)d_in[5];
    const float* Wfc = (const float*)d_in[6];
    const float* bfc = (const float*)d_in[7];
    float*       out = (float*)d_out;

    const int n = in_sizes[0] / 128;
    const int e = in_sizes[1] / 2;

    const int T = 256;
    int gn  = (n + T - 1) / T;
    int ge  = (e + T - 1) / T;
    int gg  = (n + 63) / 64;
    int gag = (n + 7) / 8;           // 8 warps per block

    // 1) CSR build + normalization
    k_init<<<gn, T>>>(ei, n);
    k_hist<<<ge, T>>>(ei, e, n);
    k_scan<<<1, 1024>>>(n);
    k_fill<<<ge, T>>>(ei, e, n);

    // 2) layer 1
    k_gemm128<<<gg, T>>>(x, W1, 1, n);                          // bufA = x @ W1
    k_aggregate<<<gag, T>>>(b1, nullptr, nullptr, nullptr, n);  // bufB = agg+b1

    // 3) layer 2 + fused classifier
    k_gemm128<<<gg, T>>>(nullptr, W2, 0, n);                    // bufA = bufB @ W2
    k_aggregate<<<gag, T>>>(b2, Wfc, bfc, out, n);              // out = (agg+b2)@Wfc+bfc
}

// round 8
// speedup vs baseline: 1.0012x; 1.0012x over previous
#include <cuda_runtime.h>
#include <cstdint>

// Problem constants (GCN_59846074302981): N=50000, E=800000, F=H=128, C=8
#define MAX_N 50000
#define MAX_E 800000

// ---------------------------------------------------------------------------
// Scratch (allocation-free device globals)
// ---------------------------------------------------------------------------
__device__ __align__(16) float g_bufA[MAX_N * 128];  // GEMM out / agg in
__device__ __align__(16) float g_bufB[MAX_N * 128];  // agg out / next GEMM in
__device__ __align__(16) float g_dinv[MAX_N];
__device__ __align__(16) float g_w[MAX_E];           // edge norm per CSR slot
__device__ int   g_count[MAX_N];                     // histogram, then fill cursor
__device__ int   g_off[MAX_N + 1];                   // CSR offsets (by dest col)
__device__ int   g_srcIdx[MAX_E];                    // source node per CSR slot
__device__ int   g_stride;                           // 1 = int32 edge data, 2 = int64

__device__ __forceinline__ int edge_at(const int* __restrict__ buf, long j, int stride) {
    return buf[j * stride];
}

// ---------------------------------------------------------------------------
// init: zero counts; warp 0 of block 0 probes edge dtype in parallel.
// int64 data with indices < 2^31 has every odd int32 word == 0.
// ---------------------------------------------------------------------------
__global__ void k_init(const int* __restrict__ ebuf, int n) {
    int i = blockIdx.x * blockDim.x + threadIdx.x;
    if (i < n) g_count[i] = 0;
    if (blockIdx.x == 0 && threadIdx.x < 32) {
        int lane = threadIdx.x;
        int nz = 0;
        #pragma unroll
        for (int t = 0; t < 8; t++)
            nz |= ebuf[2 * (lane + 32 * t) + 1];
        unsigned m = __ballot_sync(0xffffffffu, nz != 0);
        if (lane == 0) g_stride = (m == 0) ? 2 : 1;
    }
}

__global__ void k_hist(const int* __restrict__ ebuf, int e, int n) {
    int i = blockIdx.x * blockDim.x + threadIdx.x;
    if (i >= e) return;
    int st = g_stride;
    int c = edge_at(ebuf, (long)e + i, st);
    if ((unsigned)c < (unsigned)n) atomicAdd(&g_count[c], 1);
}

// Single-block scan. Also computes dinv and re-zeroes counts (fill cursors).
__global__ __launch_bounds__(1024) void k_scan(int n) {
    const int T = 1024;
    int tid  = threadIdx.x;
    int L    = (n + T - 1) / T;
    int beg  = tid * L;
    int end  = beg + L; if (end > n) end = n;

    int s = 0;
    for (int i = beg; i < end; i++) s += g_count[i];

    __shared__ int wsum[32];
    int lane = tid & 31, wid = tid >> 5;
    int v = s;
    #pragma unroll
    for (int o = 1; o < 32; o <<= 1) {
        int t = __shfl_up_sync(0xffffffffu, v, o);
        if (lane >= o) v += t;
    }
    if (lane == 31) wsum[wid] = v;
    __syncthreads();
    if (wid == 0) {
        int w = wsum[lane];
        #pragma unroll
        for (int o = 1; o < 32; o <<= 1) {
            int t = __shfl_up_sync(0xffffffffu, w, o);
            if (lane >= o) w += t;
        }
        wsum[lane] = w;
    }
    __syncthreads();

    int run = v - s + (wid ? wsum[wid - 1] : 0);
    for (int i = beg; i < end; i++) {
        int c = g_count[i];
        g_off[i]   = run;
        g_dinv[i]  = rsqrtf((float)c + 1.0f);   // +1 self-loop
        g_count[i] = 0;                          // cursor for fill
        run += c;
    }
    if (tid == T - 1) g_off[n] = run;
}

// Fill: materialize per-slot source index AND edge weight (round-3 layout).
__global__ void k_fill(const int* __restrict__ ebuf, int e, int n) {
    int i = blockIdx.x * blockDim.x + threadIdx.x;
    if (i >= e) return;
    int st = g_stride;
    int r = edge_at(ebuf, i, st);
    int c = edge_at(ebuf, (long)e + i, st);
    if ((unsigned)r >= (unsigned)n || (unsigned)c >= (unsigned)n) return;
    int slot = g_off[c] + atomicAdd(&g_count[c], 1);
    g_srcIdx[slot] = r;
    g_w[slot] = g_dinv[r] * g_dinv[c];
}

// ---------------------------------------------------------------------------
// GEMM (round-3 measured-good): 64x128 tile, BK=32, 256 thr, 4x8 per thread.
// g_bufA[n,128] = SRC[n,128] @ W[128,128]
// ---------------------------------------------------------------------------
__global__ __launch_bounds__(256) void k_gemm128(const float* __restrict__ Xext,
                                                 const float* __restrict__ W,
                                                 int use_ext, int nrows) {
    const float* __restrict__ X = use_ext ? Xext : g_bufB;
    __shared__ __align__(16) float xs[32][64 + 4];   // [k][m], padded
    __shared__ __align__(16) float ws[32][128];      // [k][n]

    const int row0 = blockIdx.x * 64;
    const int tid  = threadIdx.x;
    const int tm   = (tid >> 4) << 2;   // 0..60 step 4
    const int tn   = (tid & 15) << 3;   // 0..120 step 8

    float acc[4][8];
    #pragma unroll
    for (int i = 0; i < 4; i++)
        #pragma unroll
        for (int j = 0; j < 8; j++) acc[i][j] = 0.0f;

    for (int kk = 0; kk < 128; kk += 32) {
        #pragma unroll
        for (int i = 0; i < 2; i++) {
            int s  = tid + i * 256;      // 0..511
            int r  = s >> 3;             // 0..63
            int c4 = s & 7;              // float4 slot within 32-wide K chunk
            float4 v = make_float4(0.f, 0.f, 0.f, 0.f);
            if (row0 + r < nrows)
                v = reinterpret_cast<const float4*>(X)[(long)(row0 + r) * 32 + (kk >> 2) + c4];
            int kb = c4 << 2;
            xs[kb + 0][r] = v.x; xs[kb + 1][r] = v.y;
            xs[kb + 2][r] = v.z; xs[kb + 3][r] = v.w;
        }
        #pragma unroll
        for (int i = 0; i < 4; i++) {
            int s  = tid + i * 256;      // 0..1023
            int k  = s >> 5;             // 0..31
            int c4 = s & 31;
            reinterpret_cast<float4*>(ws[k])[c4] =
                reinterpret_cast<const float4*>(W)[(kk + k) * 32 + c4];
        }
        __syncthreads();

        #pragma unroll
        for (int k = 0; k < 32; k++) {
            float a[4] = {xs[k][tm + 0], xs[k][tm + 1], xs[k][tm + 2], xs[k][tm + 3]};
            float4 b0 = reinterpret_cast<const float4*>(ws[k])[(tn >> 2) + 0];
            float4 b1 = reinterpret_cast<const float4*>(ws[k])[(tn >> 2) + 1];
            float b[8] = {b0.x, b0.y, b0.z, b0.w, b1.x, b1.y, b1.z, b1.w};
            #pragma unroll
            for (int i = 0; i < 4; i++)
                #pragma unroll
                for (int j = 0; j < 8; j++)
                    acc[i][j] += a[i] * b[j];
        }
        __syncthreads();
    }

    #pragma unroll
    for (int i = 0; i < 4; i++) {
        int r = row0 + tm + i;
        if (r < nrows) {
            reinterpret_cast<float4*>(g_bufA)[(long)r * 32 + (tn >> 2) + 0] =
                make_float4(acc[i][0], acc[i][1], acc[i][2], acc[i][3]);
            reinterpret_cast<float4*>(g_bufA)[(long)r * 32 + (tn >> 2) + 1] =
                make_float4(acc[i][4], acc[i][5], acc[i][6], acc[i][7]);
        }
    }
}

// ---------------------------------------------------------------------------
// Aggregation (round-3 measured-good): one warp per node, lane = one float4.
// g_bufB[node] = bias + dinv^2 * g_bufA[node] + sum_e w_e * g_bufA[src_e]
// 2-way unrolled, reads materialized g_w.
// ---------------------------------------------------------------------------
__global__ __launch_bounds__(256) void k_aggregate(const float* __restrict__ bias, int n) {
    int warp = blockIdx.x * (blockDim.x >> 5) + (threadIdx.x >> 5);
    int lane = threadIdx.x & 31;
    if (warp >= n) return;

    const float4* __restrict__ h4 = reinterpret_cast<const float4*>(g_bufA);

    float d = g_dinv[warp];
    float s = d * d;
    float4 b  = reinterpret_cast<const float4*>(bias)[lane];
    float4 hv = h4[(long)warp * 32 + lane];
    float ax = b.x + s * hv.x, ay = b.y + s * hv.y;
    float az = b.z + s * hv.z, aw = b.w + s * hv.w;

    int j   = g_off[warp];
    int end = g_off[warp + 1];

    for (; j + 1 < end; j += 2) {
        int   r0 = g_srcIdx[j],     r1 = g_srcIdx[j + 1];
        float w0 = g_w[j],          w1 = g_w[j + 1];
        float4 v0 = h4[(long)r0 * 32 + lane];
        float4 v1 = h4[(long)r1 * 32 + lane];
        ax += w0 * v0.x; ay += w0 * v0.y; az += w0 * v0.z; aw += w0 * v0.w;
        ax += w1 * v1.x; ay += w1 * v1.y; az += w1 * v1.z; aw += w1 * v1.w;
    }
    if (j < end) {
        int   r0 = g_srcIdx[j];
        float w0 = g_w[j];
        float4 v0 = h4[(long)r0 * 32 + lane];
        ax += w0 * v0.x; ay += w0 * v0.y; az += w0 * v0.z; aw += w0 * v0.w;
    }

    reinterpret_cast<float4*>(g_bufB)[(long)warp * 32 + lane] = make_float4(ax, ay, az, aw);
}

// ---------------------------------------------------------------------------
// Final FC: out[n,8] = g_bufB[n,128] @ Wfc[128,8] + bfc  (round-3 version)
// ---------------------------------------------------------------------------
__global__ __launch_bounds__(256) void k_fc(const float* __restrict__ Wfc,
                                            const float* __restrict__ bfc,
                                            float* __restrict__ out, int nrows) {
    __shared__ __align__(16) float xs[32][129];
    __shared__ __align__(16) float ws[128 * 8];
    __shared__ float bs[8];

    int row0 = blockIdx.x * 32;
    int tid  = threadIdx.x;

    reinterpret_cast<float4*>(ws)[tid] = reinterpret_cast<const float4*>(Wfc)[tid];
    if (tid < 8) bs[tid] = bfc[tid];

    #pragma unroll
    for (int i = 0; i < 4; i++) {
        int s  = tid + i * 256;   // 0..1023
        int r  = s >> 5;          // 0..31
        int c4 = s & 31;
        float4 v = make_float4(0.f, 0.f, 0.f, 0.f);
        if (row0 + r < nrows)
            v = reinterpret_cast<const float4*>(g_bufB)[(long)(row0 + r) * 32 + c4];
        int cb = c4 << 2;
        xs[r][cb + 0] = v.x; xs[r][cb + 1] = v.y;
        xs[r][cb + 2] = v.z; xs[r][cb + 3] = v.w;
    }
    __syncthreads();

    int r = tid >> 3, c = tid & 7;
    float acc = 0.0f;
    #pragma unroll 16
    for (int k = 0; k < 128; k++)
        acc += xs[r][k] * ws[k * 8 + c];

    if (row0 + r < nrows)
        out[(long)(row0 + r) * 8 + c] = acc + bs[c];
}

// ---------------------------------------------------------------------------
// Launcher
// ---------------------------------------------------------------------------
extern "C" void kernel_launch(void* const* d_in, const int* in_sizes, int n_in,
                              void* d_out, int out_size) {
    const float* x   = (const float*)d_in[0];
    const int*   ei  = (const int*)d_in[1];   // int32 view; stride handles int64
    const float* W1  = (const float*)d_in[2];
    const float* b1  = (const float*)d_in[3];
    const float* W2  = (const float*)d_in[4];
    const float* b2  = (const float*)d_in[5];
    const float* Wfc = (const float*)d_in[6];
    const float* bfc = (const float*)d_in[7];
    float*       out = (float*)d_out;

    const int n = in_sizes[0] / 128;
    const int e = in_sizes[1] / 2;

    const int T = 256;
    int gn  = (n + T - 1) / T;
    int ge  = (e + T - 1) / T;
    int gg  = (n + 63) / 64;
    int gag = (n + 7) / 8;           // 8 warps per block
    int gfc = (n + 31) / 32;

    // 1) CSR build + normalization
    k_init<<<gn, T>>>(ei, n);
    k_hist<<<ge, T>>>(ei, e, n);
    k_scan<<<1, 1024>>>(n);
    k_fill<<<ge, T>>>(ei, e, n);

    // 2) layer 1
    k_gemm128<<<gg, T>>>(x, W1, 1, n);           // bufA = x @ W1
    k_aggregate<<<gag, T>>>(b1, n);              // bufB = agg(bufA) + b1

    // 3) layer 2
    k_gemm128<<<gg, T>>>(nullptr, W2, 0, n);     // bufA = bufB @ W2
    k_aggregate<<<gag, T>>>(b2, n);              // bufB = agg(bufA) + b2

    // 4) classifier
    k_fc<<<gfc, T>>>(Wfc, bfc, out, n);
}

// round 12
// speedup vs baseline: 3.1993x; 3.1953x over previous
#include <cuda_runtime.h>
#include <cstdint>

// Problem constants (GCN_59846074302981): N=50000, E=800000, F=H=128, C=8
#define MAX_N 50000
#define MAX_E 800000

// ---------------------------------------------------------------------------
// Scratch (allocation-free device globals).
// RULE (learned round 10): device globals are referenced ONLY inside kernel
// bodies — never passed as kernel arguments from host code (host sees the
// shadow copy; on GB300/ATS that silently reads/writes HOST memory).
// Linear collapse: out = A·(A·(X@Wall) + c1) + c2,
//   Wall = W1@W2@Wfc [128x8], c1 = b1@(W2@Wfc) [8], c2 = b2@Wfc + bfc [8]
// ---------------------------------------------------------------------------
__device__ __align__(16) float g_z0[MAX_N * 8];    // X @ Wall
__device__ __align__(16) float g_z1[MAX_N * 8];    // A z0 + c1
__device__ __align__(16) float g_wall[128 * 8];
__device__ __align__(16) float g_c1[8];
__device__ __align__(16) float g_c2[8];
__device__ __align__(16) float g_dinv[MAX_N];
__device__ int g_deg[MAX_N];
__device__ int g_stride;                           // 1 = int32 edges, 2 = int64

// ---------------------------------------------------------------------------
// init: zero degrees; warp 0 of block 0 probes edge dtype in parallel.
// int64 data with indices < 2^31 has every odd int32 word == 0.
// ---------------------------------------------------------------------------
__global__ void k_init(const int* __restrict__ ebuf, int n) {
    int i = blockIdx.x * blockDim.x + threadIdx.x;
    if (i < n) g_deg[i] = 0;
    if (blockIdx.x == 0 && threadIdx.x < 32) {
        int lane = threadIdx.x;
        int nz = 0;
        #pragma unroll
        for (int t = 0; t < 8; t++)
            nz |= ebuf[2 * (lane + 32 * t) + 1];
        unsigned m = __ballot_sync(0xffffffffu, nz != 0);
        if (lane == 0) g_stride = (m == 0) ? 2 : 1;
    }
}

__global__ void k_hist(const int* __restrict__ ebuf, int e, int n) {
    int i = blockIdx.x * blockDim.x + threadIdx.x;
    if (i >= e) return;
    int st = g_stride;
    int c = ebuf[((long)e + i) * st];
    if ((unsigned)c < (unsigned)n) atomicAdd(&g_deg[c], 1);
}

__global__ void k_dinv(int n) {
    int i = blockIdx.x * blockDim.x + threadIdx.x;
    if (i < n) g_dinv[i] = rsqrtf((float)g_deg[i] + 1.0f);   // +1 self-loop
}

// ---------------------------------------------------------------------------
// Precompute (1 block, 256 thr): Wall = W1@(W2@Wfc), c1 = b1@(W2@Wfc),
// c2 = b2@Wfc + bfc.
// ---------------------------------------------------------------------------
__global__ __launch_bounds__(256) void k_prep(const float* __restrict__ W1,
                                              const float* __restrict__ W2,
                                              const float* __restrict__ Wfc,
                                              const float* __restrict__ b1,
                                              const float* __restrict__ b2,
                                              const float* __restrict__ bfc) {
    __shared__ float sf[128 * 8];    // Wfc, then T = W2@Wfc
    int tid = threadIdx.x;

    for (int i = tid; i < 1024; i += 256) sf[i] = Wfc[i];
    __syncthreads();

    // T = W2 @ Wfc (into registers)
    float t[4];
    #pragma unroll
    for (int p = 0; p < 4; p++) {
        int idx = tid + p * 256;
        int k = idx >> 3, c = idx & 7;
        float s = 0.0f;
        for (int j = 0; j < 128; j++) s += W2[k * 128 + j] * sf[j * 8 + c];
        t[p] = s;
    }
    // c2 = b2 @ Wfc + bfc (reads sf = Wfc, before overwrite)
    if (tid < 8) {
        float s = bfc[tid];
        for (int j = 0; j < 128; j++) s += b2[j] * sf[j * 8 + tid];
        g_c2[tid] = s;
    }
    __syncthreads();
    #pragma unroll
    for (int p = 0; p < 4; p++) sf[tid + p * 256] = t[p];   // sf = T
    __syncthreads();

    // Wall = W1 @ T ; c1 = b1 @ T
    #pragma unroll
    for (int p = 0; p < 4; p++) {
        int idx = tid + p * 256;
        int k = idx >> 3, c = idx & 7;
        float s = 0.0f;
        for (int j = 0; j < 128; j++) s += W1[k * 128 + j] * sf[j * 8 + c];
        g_wall[idx] = s;
    }
    if (tid < 8) {
        float s = 0.0f;
        for (int j = 0; j < 128; j++) s += b1[j] * sf[j * 8 + tid];
        g_c1[tid] = s;
    }
}

// ---------------------------------------------------------------------------
// z0 = X @ Wall [n,8]; also z1 = c1 + dinv^2 * z0 (self-loop init).
// One warp per row: lane holds X[row][4*lane..4*lane+3], butterfly reduce.
// ---------------------------------------------------------------------------
__global__ __launch_bounds__(256) void k_gz0(const float* __restrict__ X, int n) {
    __shared__ __align__(16) float wsT[8][128];   // [c][k]
    __shared__ float c1s[8];
    int tid = threadIdx.x;

    for (int i = tid; i < 1024; i += 256) {
        int k = i >> 3, c = i & 7;
        wsT[c][k] = g_wall[i];
    }
    if (tid < 8) c1s[tid] = g_c1[tid];
    __syncthreads();

    int warp = blockIdx.x * 8 + (tid >> 5);
    int lane = tid & 31;
    if (warp >= n) return;

    float4 xv = reinterpret_cast<const float4*>(X)[(long)warp * 32 + lane];
    int k0 = lane << 2;

    float p[8];
    #pragma unroll
    for (int c = 0; c < 8; c++) {
        float4 w = *reinterpret_cast<const float4*>(&wsT[c][k0]);
        p[c] = xv.x * w.x + xv.y * w.y + xv.z * w.z + xv.w * w.w;
    }
    #pragma unroll
    for (int o = 16; o > 0; o >>= 1)
        #pragma unroll
        for (int c = 0; c < 8; c++)
            p[c] += __shfl_xor_sync(0xffffffffu, p[c], o);

    if (lane == 0) {
        float d = g_dinv[warp];
        float s = d * d;
        reinterpret_cast<float4*>(g_z0)[(long)warp * 2 + 0] =
            make_float4(p[0], p[1], p[2], p[3]);
        reinterpret_cast<float4*>(g_z0)[(long)warp * 2 + 1] =
            make_float4(p[4], p[5], p[6], p[7]);
        reinterpret_cast<float4*>(g_z1)[(long)warp * 2 + 0] =
            make_float4(c1s[0] + s * p[0], c1s[1] + s * p[1],
                        c1s[2] + s * p[2], c1s[3] + s * p[3]);
        reinterpret_cast<float4*>(g_z1)[(long)warp * 2 + 1] =
            make_float4(c1s[4] + s * p[4], c1s[5] + s * p[5],
                        c1s[6] + s * p[6], c1s[7] + s * p[7]);
    }
}

// ---------------------------------------------------------------------------
// Scatter: dst[col] += dinv[row]*dinv[col] * src[row]  (8-wide features).
// phase 0: src = g_z0, dst = g_z1 (both device globals, bound in-kernel)
// phase 1: src = g_z1, dst = outp (harness output pointer)
// 8 threads per edge: row/col/dinv loads broadcast within the lane group;
// gather + atomics hit whole 32B sectors.
// ---------------------------------------------------------------------------
__global__ __launch_bounds__(256) void k_scatter(const int* __restrict__ ebuf,
                                                 float* __restrict__ outp,
                                                 int phase, int e, int n) {
    const float* __restrict__ src = (phase == 0) ? g_z0 : g_z1;
    float* __restrict__ dst       = (phase == 0) ? g_z1 : outp;

    long t = (long)blockIdx.x * blockDim.x + threadIdx.x;
    int edge = (int)(t >> 3);
    int f    = (int)(t & 7);
    if (edge >= e) return;
    int st = g_stride;
    int r = ebuf[(long)edge * st];
    int c = ebuf[((long)e + edge) * st];
    if ((unsigned)r >= (unsigned)n || (unsigned)c >= (unsigned)n) return;
    float w = g_dinv[r] * g_dinv[c];
    atomicAdd(&dst[(long)c * 8 + f], w * src[(long)r * 8 + f]);
}

// ---------------------------------------------------------------------------
// Init second aggregation directly into out: out = c2 + dinv^2 * z1.
// float4 granularity (n*2 float4s).
// ---------------------------------------------------------------------------
__global__ void k_initz2(float* __restrict__ out, int n) {
    int i = blockIdx.x * blockDim.x + threadIdx.x;
    if (i >= n * 2) return;
    int node = i >> 1, half = i & 1;
    float d = g_dinv[node];
    float s = d * d;
    float4 z = reinterpret_cast<const float4*>(g_z1)[i];
    float4 c = reinterpret_cast<const float4*>(g_c2)[half];
    reinterpret_cast<float4*>(out)[i] =
        make_float4(c.x + s * z.x, c.y + s * z.y, c.z + s * z.z, c.w + s * z.w);
}

// ---------------------------------------------------------------------------
// Launcher (only harness pointers cross the host/device argument boundary)
// ---------------------------------------------------------------------------
extern "C" void kernel_launch(void* const* d_in, const int* in_sizes, int n_in,
                              void* d_out, int out_size) {
    const float* x   = (const float*)d_in[0];
    const int*   ei  = (const int*)d_in[1];   // int32 view; stride handles int64
    const float* W1  = (const float*)d_in[2];
    const float* b1  = (const float*)d_in[3];
    const float* W2  = (const float*)d_in[4];
    const float* b2  = (const float*)d_in[5];
    const float* Wfc = (const float*)d_in[6];
    const float* bfc = (const float*)d_in[7];
    float*       out = (float*)d_out;

    const int n = in_sizes[0] / 128;
    const int e = in_sizes[1] / 2;

    const int T = 256;
    int gn  = (n + T - 1) / T;
    int ge  = (e + T - 1) / T;
    int gz  = (n * 32 + T - 1) / T;              // warp per row
    int gs  = (int)(((long)e * 8 + T - 1) / T);  // 8 threads per edge
    int gi2 = (n * 2 + T - 1) / T;

    // normalization + weight collapse
    k_init<<<gn, T>>>(ei, n);
    k_hist<<<ge, T>>>(ei, e, n);
    k_dinv<<<gn, T>>>(n);
    k_prep<<<1, T>>>(W1, W2, Wfc, b1, b2, bfc);

    // z0 = X@Wall ; z1 = c1 + dinv^2 z0
    k_gz0<<<gz, T>>>(x, n);

    // z1 += A-offdiag z0   (phase 0: internal buffers)
    k_scatter<<<gs, T>>>(ei, out, 0, e, n);

    // out = c2 + dinv^2 z1 ; out += A-offdiag z1   (phase 1: dst = out)
    k_initz2<<<gi2, T>>>(out, n);
    k_scatter<<<gs, T>>>(ei, out, 1, e, n);
}

// round 14
// speedup vs baseline: 4.0800x; 1.2753x over previous
#include <cuda_runtime.h>
#include <cstdint>

// Problem constants (GCN_59846074302981): N=50000, E=800000, F=H=128, C=8
#define MAX_N 50000
#define MAX_E 800000

// ---------------------------------------------------------------------------
// Scratch (allocation-free device globals).
// RULE (learned round 10): device globals are referenced ONLY inside kernel
// bodies — never passed as kernel arguments from host code.
// Linear collapse: out = A·(A·(X@Wall) + c1) + c2,
//   Wall = W1@W2@Wfc [128x8], c1 = b1@(W2@Wfc) [8], c2 = b2@Wfc + bfc [8]
// ---------------------------------------------------------------------------
__device__ __align__(16) float g_z0[MAX_N * 8];    // X @ Wall
__device__ __align__(16) float g_z1[MAX_N * 8];    // A z0 + c1
__device__ __align__(16) float g_T[128 * 8];       // W2 @ Wfc
__device__ __align__(16) float g_wall[128 * 8];
__device__ __align__(16) float g_c1[8];
__device__ __align__(16) float g_c2[8];
__device__ __align__(16) float g_dinv[MAX_N];
__device__ int g_deg[MAX_N];
__device__ int g_stride;                           // 1 = int32 edges, 2 = int64

// ---------------------------------------------------------------------------
// init: zero degrees; warp 0 of block 0 probes edge dtype in parallel.
// int64 data with indices < 2^31 has every odd int32 word == 0.
// ---------------------------------------------------------------------------
__global__ void k_init(const int* __restrict__ ebuf, int n) {
    int i = blockIdx.x * blockDim.x + threadIdx.x;
    if (i < n) g_deg[i] = 0;
    if (blockIdx.x == 0 && threadIdx.x < 32) {
        int lane = threadIdx.x;
        int nz = 0;
        #pragma unroll
        for (int t = 0; t < 8; t++)
            nz |= ebuf[2 * (lane + 32 * t) + 1];
        unsigned m = __ballot_sync(0xffffffffu, nz != 0);
        if (lane == 0) g_stride = (m == 0) ? 2 : 1;
    }
}

__global__ void k_hist(const int* __restrict__ ebuf, int e, int n) {
    int i = blockIdx.x * blockDim.x + threadIdx.x;
    if (i >= e) return;
    int st = g_stride;
    int c = ebuf[((long)e + i) * st];
    if ((unsigned)c < (unsigned)n) atomicAdd(&g_deg[c], 1);
}

__global__ void k_dinv(int n) {
    int i = blockIdx.x * blockDim.x + threadIdx.x;
    if (i < n) g_dinv[i] = rsqrtf((float)g_deg[i] + 1.0f);   // +1 self-loop
}

// ---------------------------------------------------------------------------
// Weight collapse, stage A (parallel, warp-per-output):
//   blocks 0..127 : T[k][c] = sum_j W2[k][j] * Wfc[j][c]   (warp = k*8+c)
//   block 128     : c2[c]   = sum_j b2[j]  * Wfc[j][c] + bfc[c]
// Lane l covers j = 4l..4l+3 (float4 row load + 4 strided Wfc reads, cached).
// ---------------------------------------------------------------------------
__global__ __launch_bounds__(256) void k_prepA(const float* __restrict__ W2,
                                               const float* __restrict__ Wfc,
                                               const float* __restrict__ b2,
                                               const float* __restrict__ bfc) {
    int warp = blockIdx.x * 8 + (threadIdx.x >> 5);
    int lane = threadIdx.x & 31;
    int j0 = lane << 2;

    if (blockIdx.x < 128) {
        int k = warp >> 3, c = warp & 7;
        float4 w = reinterpret_cast<const float4*>(W2)[k * 32 + lane];
        float s = w.x * Wfc[(j0 + 0) * 8 + c] + w.y * Wfc[(j0 + 1) * 8 + c]
                + w.z * Wfc[(j0 + 2) * 8 + c] + w.w * Wfc[(j0 + 3) * 8 + c];
        #pragma unroll
        for (int o = 16; o > 0; o >>= 1) s += __shfl_xor_sync(0xffffffffu, s, o);
        if (lane == 0) g_T[k * 8 + c] = s;
    } else {
        int c = warp - 1024;   // 0..7
        float4 b = reinterpret_cast<const float4*>(b2)[lane];
        float s = b.x * Wfc[(j0 + 0) * 8 + c] + b.y * Wfc[(j0 + 1) * 8 + c]
                + b.z * Wfc[(j0 + 2) * 8 + c] + b.w * Wfc[(j0 + 3) * 8 + c];
        #pragma unroll
        for (int o = 16; o > 0; o >>= 1) s += __shfl_xor_sync(0xffffffffu, s, o);
        if (lane == 0) g_c2[c] = s + bfc[c];
    }
}

// ---------------------------------------------------------------------------
// Weight collapse, stage B:
//   blocks 0..127 : Wall[k][c] = sum_j W1[k][j] * T[j][c]
//   block 128     : c1[c]      = sum_j b1[j]  * T[j][c]
// ---------------------------------------------------------------------------
__global__ __launch_bounds__(256) void k_prepB(const float* __restrict__ W1,
                                               const float* __restrict__ b1) {
    int warp = blockIdx.x * 8 + (threadIdx.x >> 5);
    int lane = threadIdx.x & 31;
    int j0 = lane << 2;

    if (blockIdx.x < 128) {
        int k = warp >> 3, c = warp & 7;
        float4 w = reinterpret_cast<const float4*>(W1)[k * 32 + lane];
        float s = w.x * g_T[(j0 + 0) * 8 + c] + w.y * g_T[(j0 + 1) * 8 + c]
                + w.z * g_T[(j0 + 2) * 8 + c] + w.w * g_T[(j0 + 3) * 8 + c];
        #pragma unroll
        for (int o = 16; o > 0; o >>= 1) s += __shfl_xor_sync(0xffffffffu, s, o);
        if (lane == 0) g_wall[k * 8 + c] = s;
    } else {
        int c = warp - 1024;   // 0..7
        float4 b = reinterpret_cast<const float4*>(b1)[lane];
        float s = b.x * g_T[(j0 + 0) * 8 + c] + b.y * g_T[(j0 + 1) * 8 + c]
                + b.z * g_T[(j0 + 2) * 8 + c] + b.w * g_T[(j0 + 3) * 8 + c];
        #pragma unroll
        for (int o = 16; o > 0; o >>= 1) s += __shfl_xor_sync(0xffffffffu, s, o);
        if (lane == 0) g_c1[c] = s;
    }
}

// ---------------------------------------------------------------------------
// z0 = X @ Wall [n,8]; also z1 = c1 + dinv^2 * z0 (self-loop init).
// One warp per row: lane holds X[row][4*lane..4*lane+3], butterfly reduce.
// ---------------------------------------------------------------------------
__global__ __launch_bounds__(256) void k_gz0(const float* __restrict__ X, int n) {
    __shared__ __align__(16) float wsT[8][128];   // [c][k]
    __shared__ float c1s[8];
    int tid = threadIdx.x;

    for (int i = tid; i < 1024; i += 256) {
        int k = i >> 3, c = i & 7;
        wsT[c][k] = g_wall[i];
    }
    if (tid < 8) c1s[tid] = g_c1[tid];
    __syncthreads();

    int warp = blockIdx.x * 8 + (tid >> 5);
    int lane = tid & 31;
    if (warp >= n) return;

    float4 xv = reinterpret_cast<const float4*>(X)[(long)warp * 32 + lane];
    int k0 = lane << 2;

    float p[8];
    #pragma unroll
    for (int c = 0; c < 8; c++) {
        float4 w = *reinterpret_cast<const float4*>(&wsT[c][k0]);
        p[c] = xv.x * w.x + xv.y * w.y + xv.z * w.z + xv.w * w.w;
    }
    #pragma unroll
    for (int o = 16; o > 0; o >>= 1)
        #pragma unroll
        for (int c = 0; c < 8; c++)
            p[c] += __shfl_xor_sync(0xffffffffu, p[c], o);

    if (lane == 0) {
        float d = g_dinv[warp];
        float s = d * d;
        reinterpret_cast<float4*>(g_z0)[(long)warp * 2 + 0] =
            make_float4(p[0], p[1], p[2], p[3]);
        reinterpret_cast<float4*>(g_z0)[(long)warp * 2 + 1] =
            make_float4(p[4], p[5], p[6], p[7]);
        reinterpret_cast<float4*>(g_z1)[(long)warp * 2 + 0] =
            make_float4(c1s[0] + s * p[0], c1s[1] + s * p[1],
                        c1s[2] + s * p[2], c1s[3] + s * p[3]);
        reinterpret_cast<float4*>(g_z1)[(long)warp * 2 + 1] =
            make_float4(c1s[4] + s * p[4], c1s[5] + s * p[5],
                        c1s[6] + s * p[6], c1s[7] + s * p[7]);
    }
}

// ---------------------------------------------------------------------------
// Scatter: dst[col] += dinv[row]*dinv[col] * src[row]  (8-wide features).
// phase 0: src = g_z0, dst = g_z1 (device globals bound in-kernel)
// phase 1: src = g_z1, dst = outp (harness output pointer)
// 8 threads per edge: row/col/dinv loads broadcast within the lane group;
// gather + atomics hit whole 32B sectors.
// ---------------------------------------------------------------------------
__global__ __launch_bounds__(256) void k_scatter(const int* __restrict__ ebuf,
                                                 float* __restrict__ outp,
                                                 int phase, int e, int n) {
    const float* __restrict__ src = (phase == 0) ? g_z0 : g_z1;
    float* __restrict__ dst       = (phase == 0) ? g_z1 : outp;

    long t = (long)blockIdx.x * blockDim.x + threadIdx.x;
    int edge = (int)(t >> 3);
    int f    = (int)(t & 7);
    if (edge >= e) return;
    int st = g_stride;
    int r = ebuf[(long)edge * st];
    int c = ebuf[((long)e + edge) * st];
    if ((unsigned)r >= (unsigned)n || (unsigned)c >= (unsigned)n) return;
    float w = g_dinv[r] * g_dinv[c];
    atomicAdd(&dst[(long)c * 8 + f], w * src[(long)r * 8 + f]);
}

// ---------------------------------------------------------------------------
// Init second aggregation directly into out: out = c2 + dinv^2 * z1.
// float4 granularity (n*2 float4s).
// ---------------------------------------------------------------------------
__global__ void k_initz2(float* __restrict__ out, int n) {
    int i = blockIdx.x * blockDim.x + threadIdx.x;
    if (i >= n * 2) return;
    int node = i >> 1, half = i & 1;
    float d = g_dinv[node];
    float s = d * d;
    float4 z = reinterpret_cast<const float4*>(g_z1)[i];
    float4 c = reinterpret_cast<const float4*>(g_c2)[half];
    reinterpret_cast<float4*>(out)[i] =
        make_float4(c.x + s * z.x, c.y + s * z.y, c.z + s * z.z, c.w + s * z.w);
}

// ---------------------------------------------------------------------------
// Launcher (only harness pointers cross the host/device argument boundary)
// ---------------------------------------------------------------------------
extern "C" void kernel_launch(void* const* d_in, const int* in_sizes, int n_in,
                              void* d_out, int out_size) {
    const float* x   = (const float*)d_in[0];
    const int*   ei  = (const int*)d_in[1];   // int32 view; stride handles int64
    const float* W1  = (const float*)d_in[2];
    const float* b1  = (const float*)d_in[3];
    const float* W2  = (const float*)d_in[4];
    const float* b2  = (const float*)d_in[5];
    const float* Wfc = (const float*)d_in[6];
    const float* bfc = (const float*)d_in[7];
    float*       out = (float*)d_out;

    const int n = in_sizes[0] / 128;
    const int e = in_sizes[1] / 2;

    const int T = 256;
    int gn  = (n + T - 1) / T;
    int ge  = (e + T - 1) / T;
    int gz  = (n * 32 + T - 1) / T;              // warp per row
    int gs  = (int)(((long)e * 8 + T - 1) / T);  // 8 threads per edge
    int gi2 = (n * 2 + T - 1) / T;

    // normalization + weight collapse (parallel, two stages)
    k_init<<<gn, T>>>(ei, n);
    k_hist<<<ge, T>>>(ei, e, n);
    k_dinv<<<gn, T>>>(n);
    k_prepA<<<129, T>>>(W2, Wfc, b2, bfc);
    k_prepB<<<129, T>>>(W1, b1);

    // z0 = X@Wall ; z1 = c1 + dinv^2 z0
    k_gz0<<<gz, T>>>(x, n);

    // z1 += A-offdiag z0   (phase 0: internal buffers)
    k_scatter<<<gs, T>>>(ei, out, 0, e, n);

    // out = c2 + dinv^2 z1 ; out += A-offdiag z1   (phase 1: dst = out)
    k_initz2<<<gi2, T>>>(out, n);
    k_scatter<<<gs, T>>>(ei, out, 1, e, n);
}

// round 16
// speedup vs baseline: 4.7691x; 1.1689x over previous
#include <cuda_runtime.h>
#include <cstdint>

// Problem constants (GCN_59846074302981): N=50000, E=800000, F=H=128, C=8
#define MAX_N 50000
#define MAX_E 800000

// ---------------------------------------------------------------------------
// Scratch (allocation-free device globals).
// RULE (round 10): device globals referenced ONLY inside kernel bodies.
// Linear collapse: out = A·(A·(X@Wall) + c1) + c2,
//   Wall = W1@W2@Wfc [128x8], c1 = b1@(W2@Wfc) [8], c2 = b2@Wfc + bfc [8]
// ---------------------------------------------------------------------------
__device__ __align__(16) float g_z0[MAX_N * 8];    // X @ Wall
__device__ __align__(16) float g_z1[MAX_N * 8];    // A z0 + c1
__device__ __align__(16) float g_T[128 * 8];       // W2 @ Wfc
__device__ __align__(16) float g_wall[128 * 8];
__device__ __align__(16) float g_c1[8];
__device__ __align__(16) float g_c2[8];
__device__ __align__(16) float g_dinv[MAX_N];
__device__ int g_deg[MAX_N];
__device__ int g_stride;                           // 1 = int32 edges, 2 = int64

// ---------------------------------------------------------------------------
// init: zero degrees; warp 0 of block 0 probes edge dtype in parallel.
// ---------------------------------------------------------------------------
__global__ void k_init(const int* __restrict__ ebuf, int n) {
    int i = blockIdx.x * blockDim.x + threadIdx.x;
    if (i < n) g_deg[i] = 0;
    if (blockIdx.x == 0 && threadIdx.x < 32) {
        int lane = threadIdx.x;
        int nz = 0;
        #pragma unroll
        for (int t = 0; t < 8; t++)
            nz |= ebuf[2 * (lane + 32 * t) + 1];
        unsigned m = __ballot_sync(0xffffffffu, nz != 0);
        if (lane == 0) g_stride = (m == 0) ? 2 : 1;
    }
}

__global__ void k_hist(const int* __restrict__ ebuf, int e, int n) {
    int i = blockIdx.x * blockDim.x + threadIdx.x;
    if (i >= e) return;
    int st = g_stride;
    int c = ebuf[((long)e + i) * st];
    if ((unsigned)c < (unsigned)n) atomicAdd(&g_deg[c], 1);
}

// ---------------------------------------------------------------------------
// Weight collapse, stage A (warp-per-output):
//   blocks 0..127 : T[k][c] = sum_j W2[k][j] * Wfc[j][c]
//   block 128     : c2[c]   = sum_j b2[j]  * Wfc[j][c] + bfc[c]
// ---------------------------------------------------------------------------
__global__ __launch_bounds__(256) void k_prepA(const float* __restrict__ W2,
                                               const float* __restrict__ Wfc,
                                               const float* __restrict__ b2,
                                               const float* __restrict__ bfc) {
    int warp = blockIdx.x * 8 + (threadIdx.x >> 5);
    int lane = threadIdx.x & 31;
    int j0 = lane << 2;

    if (blockIdx.x < 128) {
        int k = warp >> 3, c = warp & 7;
        float4 w = reinterpret_cast<const float4*>(W2)[k * 32 + lane];
        float s = w.x * Wfc[(j0 + 0) * 8 + c] + w.y * Wfc[(j0 + 1) * 8 + c]
                + w.z * Wfc[(j0 + 2) * 8 + c] + w.w * Wfc[(j0 + 3) * 8 + c];
        #pragma unroll
        for (int o = 16; o > 0; o >>= 1) s += __shfl_xor_sync(0xffffffffu, s, o);
        if (lane == 0) g_T[k * 8 + c] = s;
    } else {
        int c = warp - 1024;   // 0..7
        float4 b = reinterpret_cast<const float4*>(b2)[lane];
        float s = b.x * Wfc[(j0 + 0) * 8 + c] + b.y * Wfc[(j0 + 1) * 8 + c]
                + b.z * Wfc[(j0 + 2) * 8 + c] + b.w * Wfc[(j0 + 3) * 8 + c];
        #pragma unroll
        for (int o = 16; o > 0; o >>= 1) s += __shfl_xor_sync(0xffffffffu, s, o);
        if (lane == 0) g_c2[c] = s + bfc[c];
    }
}

// ---------------------------------------------------------------------------
// Weight collapse, stage B:
//   blocks 0..127 : Wall[k][c] = sum_j W1[k][j] * T[j][c]
//   block 128     : c1[c]      = sum_j b1[j]  * T[j][c]
// ---------------------------------------------------------------------------
__global__ __launch_bounds__(256) void k_prepB(const float* __restrict__ W1,
                                               const float* __restrict__ b1) {
    int warp = blockIdx.x * 8 + (threadIdx.x >> 5);
    int lane = threadIdx.x & 31;
    int j0 = lane << 2;

    if (blockIdx.x < 128) {
        int k = warp >> 3, c = warp & 7;
        float4 w = reinterpret_cast<const float4*>(W1)[k * 32 + lane];
        float s = w.x * g_T[(j0 + 0) * 8 + c] + w.y * g_T[(j0 + 1) * 8 + c]
                + w.z * g_T[(j0 + 2) * 8 + c] + w.w * g_T[(j0 + 3) * 8 + c];
        #pragma unroll
        for (int o = 16; o > 0; o >>= 1) s += __shfl_xor_sync(0xffffffffu, s, o);
        if (lane == 0) g_wall[k * 8 + c] = s;
    } else {
        int c = warp - 1024;   // 0..7
        float4 b = reinterpret_cast<const float4*>(b1)[lane];
        float s = b.x * g_T[(j0 + 0) * 8 + c] + b.y * g_T[(j0 + 1) * 8 + c]
                + b.z * g_T[(j0 + 2) * 8 + c] + b.w * g_T[(j0 + 3) * 8 + c];
        #pragma unroll
        for (int o = 16; o > 0; o >>= 1) s += __shfl_xor_sync(0xffffffffu, s, o);
        if (lane == 0) g_c1[c] = s;
    }
}

// ---------------------------------------------------------------------------
// z0 = X @ Wall [n,8]; z1 = c1 + dinv^2 * z0; ALSO computes and stores
// dinv = rsqrt(deg+1) (folded from the old k_dinv — gz0 runs before any
// consumer of g_dinv).
// One warp per row: lane holds X[row][4*lane..4*lane+3], butterfly reduce.
// ---------------------------------------------------------------------------
__global__ __launch_bounds__(256) void k_gz0(const float* __restrict__ X, int n) {
    __shared__ __align__(16) float wsT[8][128];   // [c][k]
    __shared__ float c1s[8];
    int tid = threadIdx.x;

    for (int i = tid; i < 1024; i += 256) {
        int k = i >> 3, c = i & 7;
        wsT[c][k] = g_wall[i];
    }
    if (tid < 8) c1s[tid] = g_c1[tid];
    __syncthreads();

    int warp = blockIdx.x * 8 + (tid >> 5);
    int lane = tid & 31;
    if (warp >= n) return;

    float4 xv = reinterpret_cast<const float4*>(X)[(long)warp * 32 + lane];
    int k0 = lane << 2;

    float p[8];
    #pragma unroll
    for (int c = 0; c < 8; c++) {
        float4 w = *reinterpret_cast<const float4*>(&wsT[c][k0]);
        p[c] = xv.x * w.x + xv.y * w.y + xv.z * w.z + xv.w * w.w;
    }
    #pragma unroll
    for (int o = 16; o > 0; o >>= 1)
        #pragma unroll
        for (int c = 0; c < 8; c++)
            p[c] += __shfl_xor_sync(0xffffffffu, p[c], o);

    if (lane == 0) {
        float d = rsqrtf((float)g_deg[warp] + 1.0f);   // +1 self-loop
        g_dinv[warp] = d;
        float s = d * d;
        reinterpret_cast<float4*>(g_z0)[(long)warp * 2 + 0] =
            make_float4(p[0], p[1], p[2], p[3]);
        reinterpret_cast<float4*>(g_z0)[(long)warp * 2 + 1] =
            make_float4(p[4], p[5], p[6], p[7]);
        reinterpret_cast<float4*>(g_z1)[(long)warp * 2 + 0] =
            make_float4(c1s[0] + s * p[0], c1s[1] + s * p[1],
                        c1s[2] + s * p[2], c1s[3] + s * p[3]);
        reinterpret_cast<float4*>(g_z1)[(long)warp * 2 + 1] =
            make_float4(c1s[4] + s * p[4], c1s[5] + s * p[5],
                        c1s[6] + s * p[6], c1s[7] + s * p[7]);
    }
}

// ---------------------------------------------------------------------------
// Scatter: dst[col][0..7] += dinv[row]*dinv[col] * src[row][0..7].
// 2 threads per edge; each packs one half (16B) into a single
// red.global.add.v4.f32 — 4x fewer atomic messages than scalar.
// phase 0: src = g_z0, dst = g_z1 ; phase 1: src = g_z1, dst = outp.
// ---------------------------------------------------------------------------
__global__ __launch_bounds__(256) void k_scatter(const int* __restrict__ ebuf,
                                                 float* __restrict__ outp,
                                                 int phase, int e, int n) {
    const float4* __restrict__ src =
        (phase == 0) ? reinterpret_cast<const float4*>(g_z0)
                     : reinterpret_cast<const float4*>(g_z1);
    float* __restrict__ dstb = (phase == 0) ? g_z1 : outp;

    long t = (long)blockIdx.x * blockDim.x + threadIdx.x;
    int edge = (int)(t >> 1);
    int h    = (int)(t & 1);
    if (edge >= e) return;
    int st = g_stride;
    int r = ebuf[(long)edge * st];
    int c = ebuf[((long)e + edge) * st];
    if ((unsigned)r >= (unsigned)n || (unsigned)c >= (unsigned)n) return;
    float w = g_dinv[r] * g_dinv[c];
    float4 v = src[(long)r * 2 + h];
    float* dst = dstb + (long)c * 8 + h * 4;
    asm volatile("red.global.add.v4.f32 [%0], {%1, %2, %3, %4};"
                 :: "l"(dst), "f"(w * v.x), "f"(w * v.y),
                    "f"(w * v.z), "f"(w * v.w)
                 : "memory");
}

// ---------------------------------------------------------------------------
// Init second aggregation directly into out: out = c2 + dinv^2 * z1.
// ---------------------------------------------------------------------------
__global__ void k_initz2(float* __restrict__ out, int n) {
    int i = blockIdx.x * blockDim.x + threadIdx.x;
    if (i >= n * 2) return;
    int node = i >> 1, half = i & 1;
    float d = g_dinv[node];
    float s = d * d;
    float4 z = reinterpret_cast<const float4*>(g_z1)[i];
    float4 c = reinterpret_cast<const float4*>(g_c2)[half];
    reinterpret_cast<float4*>(out)[i] =
        make_float4(c.x + s * z.x, c.y + s * z.y, c.z + s * z.z, c.w + s * z.w);
}

// ---------------------------------------------------------------------------
// Launcher (only harness pointers cross the host/device argument boundary)
// ---------------------------------------------------------------------------
extern "C" void kernel_launch(void* const* d_in, const int* in_sizes, int n_in,
                              void* d_out, int out_size) {
    const float* x   = (const float*)d_in[0];
    const int*   ei  = (const int*)d_in[1];   // int32 view; stride handles int64
    const float* W1  = (const float*)d_in[2];
    const float* b1  = (const float*)d_in[3];
    const float* W2  = (const float*)d_in[4];
    const float* b2  = (const float*)d_in[5];
    const float* Wfc = (const float*)d_in[6];
    const float* bfc = (const float*)d_in[7];
    float*       out = (float*)d_out;

    const int n = in_sizes[0] / 128;
    const int e = in_sizes[1] / 2;

    const int T = 256;
    int gn  = (n + T - 1) / T;
    int ge  = (e + T - 1) / T;
    int gz  = (n * 32 + T - 1) / T;              // warp per row
    int gs  = (int)(((long)e * 2 + T - 1) / T);  // 2 threads per edge
    int gi2 = (n * 2 + T - 1) / T;

    // normalization + weight collapse
    k_init<<<gn, T>>>(ei, n);
    k_hist<<<ge, T>>>(ei, e, n);
    k_prepA<<<129, T>>>(W2, Wfc, b2, bfc);
    k_prepB<<<129, T>>>(W1, b1);

    // z0 = X@Wall ; z1 = c1 + dinv^2 z0 ; dinv computed here (from deg)
    k_gz0<<<gz, T>>>(x, n);

    // z1 += A-offdiag z0   (phase 0: internal buffers)
    k_scatter<<<gs, T>>>(ei, out, 0, e, n);

    // out = c2 + dinv^2 z1 ; out += A-offdiag z1   (phase 1: dst = out)
    k_initz2<<<gi2, T>>>(out, n);
    k_scatter<<<gs, T>>>(ei, out, 1, e, n);
}